// round 8
// baseline (speedup 1.0000x reference)
#include <cstdint>
#include <cuda_runtime.h>
#include <cuda_bf16.h>
#include <math_constants.h>

#define Bn 16
#define Sn 2048
#define Dn 768
#define D4 192                       // Dn/4
#define NORM_CONST 0.0360843918243516127f  // 1/sqrt(768)

// attn pipeline geometry
#define CHUNK_ROWS 128
#define CHUNKS_PER_B (Sn / CHUNK_ROWS)     // 16
#define NPART (Bn * CHUNKS_PER_B)          // 256 partials
#define ATT_STAGES 4
#define RPS 8                              // rows per stage
#define STAGE_F4 (RPS * D4)                // 1536 float4
#define STAGE_BYTES (STAGE_F4 * 16)        // 24576
#define NSTAGE_ITERS (CHUNK_ROWS / RPS)    // 16

// ---------------- scratch ----------------
__device__ float g_qk[Bn * Dn];
__device__ float g_pm[NPART];
__device__ float g_pl[NPART];
__device__ float g_pacc[(size_t)NPART * Dn];   // 786 KB
__device__ float g_c[Bn * Dn];

// ---------------- helpers ----------------
__device__ __forceinline__ float warp_sum(float v) {
    #pragma unroll
    for (int off = 16; off > 0; off >>= 1)
        v += __shfl_xor_sync(0xffffffffu, v, off);
    return v;
}

__device__ __forceinline__ void cp_async16(unsigned int dst, const void* src) {
    asm volatile("cp.async.cg.shared.global [%0], [%1], 16;" :: "r"(dst), "l"(src));
}
__device__ __forceinline__ void cp_commit() {
    asm volatile("cp.async.commit_group;");
}
__device__ __forceinline__ void cp_wait_all() {
    asm volatile("cp.async.wait_group 0;");
}

// ============ K1: fused q0 = Wq x0, qk += Wk^T q0 (per e-tile, atomic) ============
// grid 96 blocks; e-tile = 8 rows; Wq and Wk each streamed from DRAM exactly once.
__global__ void __launch_bounds__(256) fused_q0qk(
    float* __restrict__ qk, const float* __restrict__ Wq,
    const float* __restrict__ Wk, const float* __restrict__ b_in)
{
    extern __shared__ float xs[];             // 48 KB: x0 for all 16 batches
    __shared__ float q0s[8 * Bn];             // q0 tile [e_local][b]
    int tid = threadIdx.x, warp = tid >> 5, lane = tid & 31;
    int e0 = blockIdx.x * 8;

    // async preload of the 16 x0 rows (each row: 192 float4, contiguous)
    {
        unsigned int sb = (unsigned int)__cvta_generic_to_shared(xs);
        const float4* src4 = (const float4*)b_in;
        #pragma unroll
        for (int i = 0; i < 12; i++) {
            int idx = i * 256 + tid;          // 0..3071
            int b = idx / D4, d4 = idx - b * D4;
            cp_async16(sb + idx * 16, src4 + (size_t)b * Sn * D4 + d4);
        }
        cp_commit();
    }

    // overlap: load this warp's Wq row into registers
    int e = e0 + warp;
    const float4* wr = (const float4*)(Wq + (size_t)e * Dn);
    float4 wf[6];
    #pragma unroll
    for (int i = 0; i < 6; i++) wf[i] = wr[i * 32 + lane];

    cp_wait_all();
    __syncthreads();

    // phase 1: warp w computes q0[e0+w][b] for all b
    {
        const float4* xs4 = (const float4*)xs;
        float acc[Bn];
        #pragma unroll
        for (int b = 0; b < Bn; b++) acc[b] = 0.f;
        #pragma unroll
        for (int i = 0; i < 6; i++) {
            float4 w = wf[i];
            #pragma unroll
            for (int b = 0; b < Bn; b++) {
                float4 x = xs4[b * D4 + i * 32 + lane];
                acc[b] = fmaf(w.x, x.x, fmaf(w.y, x.y, fmaf(w.z, x.z, fmaf(w.w, x.w, acc[b]))));
            }
        }
        #pragma unroll
        for (int b = 0; b < Bn; b++) {
            float v = warp_sum(acc[b]);
            if (lane == 0) q0s[warp * Bn + b] = v;
        }
    }
    __syncthreads();

    // phase 2: partial qk[b][d] += sum_{e in tile} q0[e][b] * Wk[e][d]
    {
        float a0[Bn], a1[Bn], a2[Bn];
        #pragma unroll
        for (int b = 0; b < Bn; b++) { a0[b] = a1[b] = a2[b] = 0.f; }
        #pragma unroll
        for (int ee = 0; ee < 8; ee++) {
            const float* wkr = Wk + (size_t)(e0 + ee) * Dn;
            float w0 = wkr[tid], w1 = wkr[tid + 256], w2 = wkr[tid + 512];
            #pragma unroll
            for (int b = 0; b < Bn; b++) {
                float q = q0s[ee * Bn + b];
                a0[b] = fmaf(q, w0, a0[b]);
                a1[b] = fmaf(q, w1, a1[b]);
                a2[b] = fmaf(q, w2, a2[b]);
            }
        }
        #pragma unroll
        for (int b = 0; b < Bn; b++) {
            atomicAdd(&qk[b * Dn + tid],       a0[b]);
            atomicAdd(&qk[b * Dn + tid + 256], a1[b]);
            atomicAdd(&qk[b * Dn + tid + 512], a2[b]);
        }
    }
}

// ============ K2: streaming online-softmax, cp.async 4-stage pipeline ============
// 256 blocks x 256 threads; block = (batch b, chunk c of 128 rows).
__global__ void __launch_bounds__(256, 2) attn_stream(
    const float* __restrict__ b_in, const float* __restrict__ qk)
{
    extern __shared__ float4 smem4[];          // 96 KB: 4 stages x 8 rows
    __shared__ float msm[8], lsm[8];
    int tid = threadIdx.x, warp = tid >> 5, lane = tid & 31;
    int b = blockIdx.x >> 4, c = blockIdx.x & (CHUNKS_PER_B - 1);

    const float4* qkv = (const float4*)(qk + b * Dn);
    float4 qf[6];
    #pragma unroll
    for (int i = 0; i < 6; i++) qf[i] = qkv[i * 32 + lane];

    const float4* xb4 = (const float4*)b_in + ((size_t)b * Sn + (size_t)c * CHUNK_ROWS) * D4;
    unsigned int sbase = (unsigned int)__cvta_generic_to_shared(smem4);

    // prologue: fill stages 0..2
    #pragma unroll
    for (int s = 0; s < ATT_STAGES - 1; s++) {
        const float4* src = xb4 + (size_t)s * STAGE_F4;
        unsigned int dst = sbase + s * STAGE_BYTES;
        #pragma unroll
        for (int i = 0; i < 6; i++) {
            int idx = i * 256 + tid;
            cp_async16(dst + idx * 16, src + idx);
        }
        cp_commit();
    }

    float m = -CUDART_INF_F, l = 0.f;
    float4 acc[6];
    #pragma unroll
    for (int i = 0; i < 6; i++) acc[i] = make_float4(0.f, 0.f, 0.f, 0.f);

    for (int t = 0; t < NSTAGE_ITERS; t++) {
        if (t + ATT_STAGES - 1 < NSTAGE_ITERS) {
            int sn = t + ATT_STAGES - 1;
            const float4* src = xb4 + (size_t)sn * STAGE_F4;
            unsigned int dst = sbase + (sn & (ATT_STAGES - 1)) * STAGE_BYTES;
            #pragma unroll
            for (int i = 0; i < 6; i++) {
                int idx = i * 256 + tid;
                cp_async16(dst + idx * 16, src + idx);
            }
        }
        cp_commit();
        asm volatile("cp.async.wait_group 3;");
        __syncthreads();

        // warp w consumes row w of stage t
        const float4* row = smem4 + (size_t)(t & (ATT_STAGES - 1)) * STAGE_F4 + warp * D4;
        float4 cur[6];
        #pragma unroll
        for (int i = 0; i < 6; i++) cur[i] = row[i * 32 + lane];

        float dot = 0.f;
        #pragma unroll
        for (int i = 0; i < 6; i++) {
            dot = fmaf(qf[i].x, cur[i].x, dot);
            dot = fmaf(qf[i].y, cur[i].y, dot);
            dot = fmaf(qf[i].z, cur[i].z, dot);
            dot = fmaf(qf[i].w, cur[i].w, dot);
        }
        float score = warp_sum(dot) * NORM_CONST;

        float mn = fmaxf(m, score);
        float corr = __expf(m - mn);       // first row: exp(-inf)=0
        float w = __expf(score - mn);
        l = l * corr + w;
        #pragma unroll
        for (int i = 0; i < 6; i++) {
            acc[i].x = fmaf(w, cur[i].x, acc[i].x * corr);
            acc[i].y = fmaf(w, cur[i].y, acc[i].y * corr);
            acc[i].z = fmaf(w, cur[i].z, acc[i].z * corr);
            acc[i].w = fmaf(w, cur[i].w, acc[i].w * corr);
        }
        m = mn;
        __syncthreads();   // protect stage before next refill
    }

    // in-block merge of 8 warp partials -> 1 block partial
    float4* accsm = smem4;   // reuse stage memory (all stages consumed; sync above)
    #pragma unroll
    for (int i = 0; i < 6; i++) accsm[warp * D4 + i * 32 + lane] = acc[i];
    if (lane == 0) { msm[warp] = m; lsm[warp] = l; }
    __syncthreads();

    if (tid < D4) {
        float M = -CUDART_INF_F;
        #pragma unroll
        for (int w = 0; w < 8; w++) M = fmaxf(M, msm[w]);
        float L = 0.f;
        float4 s = make_float4(0.f, 0.f, 0.f, 0.f);
        #pragma unroll
        for (int w = 0; w < 8; w++) {
            float ef = __expf(msm[w] - M);
            L = fmaf(ef, lsm[w], L);
            float4 a = accsm[w * D4 + tid];
            s.x = fmaf(ef, a.x, s.x);
            s.y = fmaf(ef, a.y, s.y);
            s.z = fmaf(ef, a.z, s.z);
            s.w = fmaf(ef, a.w, s.w);
        }
        ((float4*)g_pacc)[(size_t)blockIdx.x * D4 + tid] = s;
        if (tid == 0) { g_pm[blockIdx.x] = M; g_pl[blockIdx.x] = L; }
    }
}

// ============ K3: split-softmax combine (16 partials/batch) ============
__global__ void __launch_bounds__(256) combine2(float* __restrict__ c)
{
    int b = blockIdx.y;
    int d = blockIdx.x * 256 + threadIdx.x;
    const float* pm = g_pm + b * CHUNKS_PER_B;
    const float* pl = g_pl + b * CHUNKS_PER_B;

    float M = -CUDART_INF_F;
    #pragma unroll
    for (int j = 0; j < CHUNKS_PER_B; j++) M = fmaxf(M, pm[j]);

    float L = 0.f, s = 0.f;
    #pragma unroll
    for (int j = 0; j < CHUNKS_PER_B; j++) {
        float ef = __expf(pm[j] - M);
        L = fmaf(ef, pl[j], L);
        s = fmaf(ef, g_pacc[((size_t)(b * CHUNKS_PER_B + j)) * Dn + d], s);
    }
    c[b * Dn + d] = s / L;
}

// ============ K4: out[b][e] = Wv[e][:] . c[b][:]  (e x d-half split) ============
// 192 blocks x 8 warps: warp (w&3) = e-row, (w>>2) = d-half; 2 blocks/SM
// co-resident to hide the cp.async preload + reduce tails; Wv streamed once.
__global__ void __launch_bounds__(256, 2) matvec_wv(
    float* __restrict__ out, const float* __restrict__ W,
    const float* __restrict__ X)
{
    extern __shared__ float xs[];             // 48 KB: c for all 16 batches
    __shared__ float psum[8][Bn];
    int tid = threadIdx.x, warp = tid >> 5, lane = tid & 31;

    {
        unsigned int sb = (unsigned int)__cvta_generic_to_shared(xs);
        const float4* src4 = (const float4*)X;
        #pragma unroll
        for (int i = 0; i < 12; i++) {
            int idx = i * 256 + tid;          // 0..3071 float4
            cp_async16(sb + idx * 16, src4 + idx);
        }
        cp_commit();
    }

    int e = blockIdx.x * 4 + (warp & 3);
    int half = warp >> 2;
    const float4* wr = (const float4*)(W + (size_t)e * Dn) + half * 96;
    float4 wf[3];
    #pragma unroll
    for (int i = 0; i < 3; i++) wf[i] = wr[i * 32 + lane];

    cp_wait_all();
    __syncthreads();

    const float4* xs4 = (const float4*)xs;
    float acc[Bn];
    #pragma unroll
    for (int b = 0; b < Bn; b++) acc[b] = 0.f;
    #pragma unroll
    for (int i = 0; i < 3; i++) {
        float4 w = wf[i];
        #pragma unroll
        for (int b = 0; b < Bn; b++) {
            float4 x = xs4[b * D4 + half * 96 + i * 32 + lane];
            acc[b] = fmaf(w.x, x.x, fmaf(w.y, x.y, fmaf(w.z, x.z, fmaf(w.w, x.w, acc[b]))));
        }
    }
    #pragma unroll
    for (int b = 0; b < Bn; b++) {
        float v = warp_sum(acc[b]);
        if (lane == 0) psum[warp][b] = v;
    }
    __syncthreads();

    if (tid < 64) {
        int el = tid >> 4, b = tid & 15;
        out[b * Dn + blockIdx.x * 4 + el] = psum[el][b] + psum[el + 4][b];
    }
}

// ---------------- launch ----------------
extern "C" void kernel_launch(void* const* d_in, const int* in_sizes, int n_in,
                              void* d_out, int out_size)
{
    const float* b_in = (const float*)d_in[0];
    // d_in[1] = mask (int64): masks whole QUERY rows only; query row 0 is always
    // unmasked and the output only uses query row 0 -> mask is irrelevant.
    const float* Wq = (const float*)d_in[2];
    const float* Wk = (const float*)d_in[3];
    const float* Wv = (const float*)d_in[4];
    float* out = (float*)d_out;

    float* qk; cudaGetSymbolAddress((void**)&qk, g_qk);
    float* cc; cudaGetSymbolAddress((void**)&cc, g_c);

    cudaFuncSetAttribute(fused_q0qk, cudaFuncAttributeMaxDynamicSharedMemorySize, 49152);
    cudaFuncSetAttribute(attn_stream, cudaFuncAttributeMaxDynamicSharedMemorySize, ATT_STAGES * STAGE_BYTES);
    cudaFuncSetAttribute(matvec_wv, cudaFuncAttributeMaxDynamicSharedMemorySize, 49152);

    cudaMemsetAsync(qk, 0, Bn * Dn * sizeof(float), 0);
    fused_q0qk<<<96, 256, 49152>>>(qk, Wq, Wk, b_in);
    attn_stream<<<NPART, 256, ATT_STAGES * STAGE_BYTES>>>(b_in, qk);
    combine2<<<dim3(3, Bn), 256>>>(cc);
    matvec_wv<<<192, 256, 49152>>>(out, Wv, cc);
}

// round 10
// speedup vs baseline: 1.4029x; 1.4029x over previous
#include <cstdint>
#include <cuda_runtime.h>
#include <cuda_bf16.h>
#include <math_constants.h>

#define Bn 16
#define Sn 2048
#define Dn 768
#define D4 192                       // Dn/4
#define NORM_CONST 0.0360843918243516127f  // 1/sqrt(768)

// attn pipeline geometry
#define CHUNK_ROWS 128
#define CHUNKS_PER_B (Sn / CHUNK_ROWS)     // 16
#define NPART (Bn * CHUNKS_PER_B)          // 256 partials
#define ATT_STAGES 4
#define RPS 8                              // rows per stage
#define STAGE_F4 (RPS * D4)                // 1536 float4
#define STAGE_BYTES (STAGE_F4 * 16)        // 24576
#define NSTAGE_ITERS (CHUNK_ROWS / RPS)    // 16

// ---------------- scratch ----------------
__device__ float g_qk[Bn * Dn];
__device__ float g_pm[NPART];
__device__ float g_pl[NPART];
__device__ float g_pacc[(size_t)NPART * Dn];   // 786 KB
__device__ float g_c[Bn * Dn];

// ---------------- helpers ----------------
__device__ __forceinline__ float warp_sum(float v) {
    #pragma unroll
    for (int off = 16; off > 0; off >>= 1)
        v += __shfl_xor_sync(0xffffffffu, v, off);
    return v;
}

__device__ __forceinline__ void cp_async16(unsigned int dst, const void* src) {
    asm volatile("cp.async.cg.shared.global [%0], [%1], 16;" :: "r"(dst), "l"(src));
}
__device__ __forceinline__ void cp_commit() {
    asm volatile("cp.async.commit_group;");
}
__device__ __forceinline__ void cp_wait_all() {
    asm volatile("cp.async.wait_group 0;");
}

// ============ K1: fused q0 = Wq x0, qk += Wk^T q0 (per e-tile, atomic) ============
// grid 96 blocks; e-tile = 8 rows; Wq and Wk each streamed from DRAM exactly once.
__global__ void __launch_bounds__(256) fused_q0qk(
    float* __restrict__ qk, const float* __restrict__ Wq,
    const float* __restrict__ Wk, const float* __restrict__ b_in)
{
    extern __shared__ float xs[];             // 48 KB: x0 for all 16 batches
    __shared__ float q0s[8 * Bn];             // q0 tile [e_local][b]
    int tid = threadIdx.x, warp = tid >> 5, lane = tid & 31;
    int e0 = blockIdx.x * 8;

    // async preload of the 16 x0 rows (each row: 192 float4, contiguous)
    {
        unsigned int sb = (unsigned int)__cvta_generic_to_shared(xs);
        const float4* src4 = (const float4*)b_in;
        #pragma unroll
        for (int i = 0; i < 12; i++) {
            int idx = i * 256 + tid;          // 0..3071
            int b = idx / D4, d4 = idx - b * D4;
            cp_async16(sb + idx * 16, src4 + (size_t)b * Sn * D4 + d4);
        }
        cp_commit();
    }

    // overlap: load this warp's Wq row into registers
    int e = e0 + warp;
    const float4* wr = (const float4*)(Wq + (size_t)e * Dn);
    float4 wf[6];
    #pragma unroll
    for (int i = 0; i < 6; i++) wf[i] = wr[i * 32 + lane];

    cp_wait_all();
    __syncthreads();

    // phase 1: warp w computes q0[e0+w][b] for all b
    {
        const float4* xs4 = (const float4*)xs;
        float acc[Bn];
        #pragma unroll
        for (int b = 0; b < Bn; b++) acc[b] = 0.f;
        #pragma unroll
        for (int i = 0; i < 6; i++) {
            float4 w = wf[i];
            #pragma unroll
            for (int b = 0; b < Bn; b++) {
                float4 x = xs4[b * D4 + i * 32 + lane];
                acc[b] = fmaf(w.x, x.x, fmaf(w.y, x.y, fmaf(w.z, x.z, fmaf(w.w, x.w, acc[b]))));
            }
        }
        #pragma unroll
        for (int b = 0; b < Bn; b++) {
            float v = warp_sum(acc[b]);
            if (lane == 0) q0s[warp * Bn + b] = v;
        }
    }
    __syncthreads();

    // phase 2: partial qk[b][d] += sum_{e in tile} q0[e][b] * Wk[e][d]
    {
        float a0[Bn], a1[Bn], a2[Bn];
        #pragma unroll
        for (int b = 0; b < Bn; b++) { a0[b] = a1[b] = a2[b] = 0.f; }
        #pragma unroll
        for (int ee = 0; ee < 8; ee++) {
            const float* wkr = Wk + (size_t)(e0 + ee) * Dn;
            float w0 = wkr[tid], w1 = wkr[tid + 256], w2 = wkr[tid + 512];
            #pragma unroll
            for (int b = 0; b < Bn; b++) {
                float q = q0s[ee * Bn + b];
                a0[b] = fmaf(q, w0, a0[b]);
                a1[b] = fmaf(q, w1, a1[b]);
                a2[b] = fmaf(q, w2, a2[b]);
            }
        }
        #pragma unroll
        for (int b = 0; b < Bn; b++) {
            atomicAdd(&qk[b * Dn + tid],       a0[b]);
            atomicAdd(&qk[b * Dn + tid + 256], a1[b]);
            atomicAdd(&qk[b * Dn + tid + 512], a2[b]);
        }
    }
}

// ============ K2: streaming online-softmax, cp.async 4-stage pipeline ============
// 256 blocks x 256 threads; block = (batch b, chunk c of 128 rows).
__global__ void __launch_bounds__(256, 2) attn_stream(
    const float* __restrict__ b_in, const float* __restrict__ qk)
{
    extern __shared__ float4 smem4[];          // 96 KB: 4 stages x 8 rows
    __shared__ float msm[8], lsm[8];
    int tid = threadIdx.x, warp = tid >> 5, lane = tid & 31;
    int b = blockIdx.x >> 4, c = blockIdx.x & (CHUNKS_PER_B - 1);

    const float4* qkv = (const float4*)(qk + b * Dn);
    float4 qf[6];
    #pragma unroll
    for (int i = 0; i < 6; i++) qf[i] = qkv[i * 32 + lane];

    const float4* xb4 = (const float4*)b_in + ((size_t)b * Sn + (size_t)c * CHUNK_ROWS) * D4;
    unsigned int sbase = (unsigned int)__cvta_generic_to_shared(smem4);

    // prologue: fill stages 0..2
    #pragma unroll
    for (int s = 0; s < ATT_STAGES - 1; s++) {
        const float4* src = xb4 + (size_t)s * STAGE_F4;
        unsigned int dst = sbase + s * STAGE_BYTES;
        #pragma unroll
        for (int i = 0; i < 6; i++) {
            int idx = i * 256 + tid;
            cp_async16(dst + idx * 16, src + idx);
        }
        cp_commit();
    }

    float m = -CUDART_INF_F, l = 0.f;
    float4 acc[6];
    #pragma unroll
    for (int i = 0; i < 6; i++) acc[i] = make_float4(0.f, 0.f, 0.f, 0.f);

    for (int t = 0; t < NSTAGE_ITERS; t++) {
        if (t + ATT_STAGES - 1 < NSTAGE_ITERS) {
            int sn = t + ATT_STAGES - 1;
            const float4* src = xb4 + (size_t)sn * STAGE_F4;
            unsigned int dst = sbase + (sn & (ATT_STAGES - 1)) * STAGE_BYTES;
            #pragma unroll
            for (int i = 0; i < 6; i++) {
                int idx = i * 256 + tid;
                cp_async16(dst + idx * 16, src + idx);
            }
        }
        cp_commit();
        asm volatile("cp.async.wait_group 3;");
        __syncthreads();

        // warp w consumes row w of stage t
        const float4* row = smem4 + (size_t)(t & (ATT_STAGES - 1)) * STAGE_F4 + warp * D4;
        float4 cur[6];
        #pragma unroll
        for (int i = 0; i < 6; i++) cur[i] = row[i * 32 + lane];

        float dot = 0.f;
        #pragma unroll
        for (int i = 0; i < 6; i++) {
            dot = fmaf(qf[i].x, cur[i].x, dot);
            dot = fmaf(qf[i].y, cur[i].y, dot);
            dot = fmaf(qf[i].z, cur[i].z, dot);
            dot = fmaf(qf[i].w, cur[i].w, dot);
        }
        float score = warp_sum(dot) * NORM_CONST;

        float mn = fmaxf(m, score);
        float corr = __expf(m - mn);       // first row: exp(-inf)=0
        float w = __expf(score - mn);
        l = l * corr + w;
        #pragma unroll
        for (int i = 0; i < 6; i++) {
            acc[i].x = fmaf(w, cur[i].x, acc[i].x * corr);
            acc[i].y = fmaf(w, cur[i].y, acc[i].y * corr);
            acc[i].z = fmaf(w, cur[i].z, acc[i].z * corr);
            acc[i].w = fmaf(w, cur[i].w, acc[i].w * corr);
        }
        m = mn;
        __syncthreads();   // protect stage before next refill
    }

    // in-block merge of 8 warp partials -> 1 block partial
    float4* accsm = smem4;   // reuse stage memory (all stages consumed; sync above)
    #pragma unroll
    for (int i = 0; i < 6; i++) accsm[warp * D4 + i * 32 + lane] = acc[i];
    if (lane == 0) { msm[warp] = m; lsm[warp] = l; }
    __syncthreads();

    if (tid < D4) {
        float M = -CUDART_INF_F;
        #pragma unroll
        for (int w = 0; w < 8; w++) M = fmaxf(M, msm[w]);
        float L = 0.f;
        float4 s = make_float4(0.f, 0.f, 0.f, 0.f);
        #pragma unroll
        for (int w = 0; w < 8; w++) {
            float ef = __expf(msm[w] - M);
            L = fmaf(ef, lsm[w], L);
            float4 a = accsm[w * D4 + tid];
            s.x = fmaf(ef, a.x, s.x);
            s.y = fmaf(ef, a.y, s.y);
            s.z = fmaf(ef, a.z, s.z);
            s.w = fmaf(ef, a.w, s.w);
        }
        ((float4*)g_pacc)[(size_t)blockIdx.x * D4 + tid] = s;
        if (tid == 0) { g_pm[blockIdx.x] = M; g_pl[blockIdx.x] = L; }
    }
}

// ============ K3: split-softmax combine (16 partials/batch, float4) ============
// 16 blocks (one per batch) x 192 threads (one per d4 column); 16 unrolled
// float4 loads per thread = 256 B in flight/thread.
__global__ void __launch_bounds__(192) combine2(float* __restrict__ c)
{
    int b = blockIdx.x;
    int d4 = threadIdx.x;                 // 0..191
    const float* pm = g_pm + b * CHUNKS_PER_B;
    const float* pl = g_pl + b * CHUNKS_PER_B;

    float M = -CUDART_INF_F;
    #pragma unroll
    for (int j = 0; j < CHUNKS_PER_B; j++) M = fmaxf(M, pm[j]);

    float L = 0.f;
    float4 s = make_float4(0.f, 0.f, 0.f, 0.f);
    const float4* pacc4 = (const float4*)g_pacc;
    #pragma unroll
    for (int j = 0; j < CHUNKS_PER_B; j++) {
        float ef = __expf(pm[j] - M);
        L = fmaf(ef, pl[j], L);
        float4 a = pacc4[(size_t)(b * CHUNKS_PER_B + j) * D4 + d4];
        s.x = fmaf(ef, a.x, s.x);
        s.y = fmaf(ef, a.y, s.y);
        s.z = fmaf(ef, a.z, s.z);
        s.w = fmaf(ef, a.w, s.w);
    }
    float inv = 1.f / L;
    float4 r = make_float4(s.x * inv, s.y * inv, s.z * inv, s.w * inv);
    ((float4*)c)[b * D4 + d4] = r;
}

// ============ K4: out[b][e] = Wv[e][:] . c[b][:]  ============
// 96 blocks x 8 warps, warp = one e-row; c preloaded via cp.async float4
// (12/thread, one latency exposure), overlapped with Wv register loads.
__global__ void __launch_bounds__(256) matvec_wv(
    float* __restrict__ out, const float* __restrict__ W,
    const float* __restrict__ X)
{
    extern __shared__ float xs[];             // 48 KB: c for all 16 batches
    int tid = threadIdx.x, warp = tid >> 5, lane = tid & 31;

    {
        unsigned int sb = (unsigned int)__cvta_generic_to_shared(xs);
        const float4* src4 = (const float4*)X;
        #pragma unroll
        for (int i = 0; i < 12; i++) {
            int idx = i * 256 + tid;          // 0..3071 float4
            cp_async16(sb + idx * 16, src4 + idx);
        }
        cp_commit();
    }

    int e = blockIdx.x * 8 + warp;
    const float4* wr = (const float4*)(W + (size_t)e * Dn);
    float4 wf[6];
    #pragma unroll
    for (int i = 0; i < 6; i++) wf[i] = wr[i * 32 + lane];

    cp_wait_all();
    __syncthreads();

    const float4* xs4 = (const float4*)xs;
    float acc[Bn];
    #pragma unroll
    for (int b = 0; b < Bn; b++) acc[b] = 0.f;
    #pragma unroll
    for (int i = 0; i < 6; i++) {
        float4 w = wf[i];
        #pragma unroll
        for (int b = 0; b < Bn; b++) {
            float4 x = xs4[b * D4 + i * 32 + lane];
            acc[b] = fmaf(w.x, x.x, fmaf(w.y, x.y, fmaf(w.z, x.z, fmaf(w.w, x.w, acc[b]))));
        }
    }
    #pragma unroll
    for (int b = 0; b < Bn; b++) {
        float v = warp_sum(acc[b]);
        if (lane == 0) out[b * Dn + e] = v;
    }
}

// ---------------- launch ----------------
extern "C" void kernel_launch(void* const* d_in, const int* in_sizes, int n_in,
                              void* d_out, int out_size)
{
    const float* b_in = (const float*)d_in[0];
    // d_in[1] = mask (int64): masks whole QUERY rows only; query row 0 is always
    // unmasked and the output only uses query row 0 -> mask is irrelevant.
    const float* Wq = (const float*)d_in[2];
    const float* Wk = (const float*)d_in[3];
    const float* Wv = (const float*)d_in[4];
    float* out = (float*)d_out;

    float* qk; cudaGetSymbolAddress((void**)&qk, g_qk);
    float* cc; cudaGetSymbolAddress((void**)&cc, g_c);

    cudaFuncSetAttribute(fused_q0qk, cudaFuncAttributeMaxDynamicSharedMemorySize, 49152);
    cudaFuncSetAttribute(attn_stream, cudaFuncAttributeMaxDynamicSharedMemorySize, ATT_STAGES * STAGE_BYTES);
    cudaFuncSetAttribute(matvec_wv, cudaFuncAttributeMaxDynamicSharedMemorySize, 49152);

    cudaMemsetAsync(qk, 0, Bn * Dn * sizeof(float), 0);
    fused_q0qk<<<96, 256, 49152>>>(qk, Wq, Wk, b_in);
    attn_stream<<<NPART, 256, ATT_STAGES * STAGE_BYTES>>>(b_in, qk);
    combine2<<<Bn, 192>>>(cc);
    matvec_wv<<<96, 256, 49152>>>(out, Wv, cc);
}

// round 11
// speedup vs baseline: 1.4885x; 1.0611x over previous
#include <cstdint>
#include <cuda_runtime.h>
#include <cuda_bf16.h>
#include <math_constants.h>

#define Bn 16
#define Sn 2048
#define Dn 768
#define D4 192                       // Dn/4
#define NORM_CONST 0.0360843918243516127f  // 1/sqrt(768)

// attn pipeline geometry
#define CHUNK_ROWS 128
#define CHUNKS_PER_B (Sn / CHUNK_ROWS)     // 16
#define NPART (Bn * CHUNKS_PER_B)          // 256 partials
#define ATT_STAGES 4
#define RPS 8                              // rows per stage
#define STAGE_F4 (RPS * D4)                // 1536 float4
#define STAGE_BYTES (STAGE_F4 * 16)        // 24576
#define NSTAGE_ITERS (CHUNK_ROWS / RPS)    // 16

// ---------------- scratch ----------------
__device__ float g_qk[Bn * Dn];
__device__ float g_pm[NPART];
__device__ float g_pl[NPART];
__device__ float g_pacc[(size_t)NPART * Dn];   // 786 KB
__device__ float g_c[Bn * Dn];

// ---------------- helpers ----------------
__device__ __forceinline__ float warp_sum(float v) {
    #pragma unroll
    for (int off = 16; off > 0; off >>= 1)
        v += __shfl_xor_sync(0xffffffffu, v, off);
    return v;
}

__device__ __forceinline__ void cp_async16(unsigned int dst, const void* src) {
    asm volatile("cp.async.cg.shared.global [%0], [%1], 16;" :: "r"(dst), "l"(src));
}
__device__ __forceinline__ void cp_commit() {
    asm volatile("cp.async.commit_group;");
}
__device__ __forceinline__ void cp_wait_all() {
    asm volatile("cp.async.wait_group 0;");
}

// ============ K1: fused q0 = Wq x0, qk += Wk^T q0 (per e-tile, atomic) ============
// grid 96 blocks; e-tile = 8 rows; Wq and Wk each streamed from DRAM exactly once.
__global__ void __launch_bounds__(256) fused_q0qk(
    float* __restrict__ qk, const float* __restrict__ Wq,
    const float* __restrict__ Wk, const float* __restrict__ b_in)
{
    extern __shared__ float xs[];             // 48 KB: x0 for all 16 batches
    __shared__ float q0s[8 * Bn];             // q0 tile [e_local][b]
    int tid = threadIdx.x, warp = tid >> 5, lane = tid & 31;
    int e0 = blockIdx.x * 8;

    // async preload of the 16 x0 rows (each row: 192 float4, contiguous)
    {
        unsigned int sb = (unsigned int)__cvta_generic_to_shared(xs);
        const float4* src4 = (const float4*)b_in;
        #pragma unroll
        for (int i = 0; i < 12; i++) {
            int idx = i * 256 + tid;          // 0..3071
            int b = idx / D4, d4 = idx - b * D4;
            cp_async16(sb + idx * 16, src4 + (size_t)b * Sn * D4 + d4);
        }
        cp_commit();
    }

    // overlap: load this warp's Wq row into registers
    int e = e0 + warp;
    const float4* wr = (const float4*)(Wq + (size_t)e * Dn);
    float4 wf[6];
    #pragma unroll
    for (int i = 0; i < 6; i++) wf[i] = wr[i * 32 + lane];

    cp_wait_all();
    __syncthreads();

    // phase 1: warp w computes q0[e0+w][b] for all b
    {
        const float4* xs4 = (const float4*)xs;
        float acc[Bn];
        #pragma unroll
        for (int b = 0; b < Bn; b++) acc[b] = 0.f;
        #pragma unroll
        for (int i = 0; i < 6; i++) {
            float4 w = wf[i];
            #pragma unroll
            for (int b = 0; b < Bn; b++) {
                float4 x = xs4[b * D4 + i * 32 + lane];
                acc[b] = fmaf(w.x, x.x, fmaf(w.y, x.y, fmaf(w.z, x.z, fmaf(w.w, x.w, acc[b]))));
            }
        }
        #pragma unroll
        for (int b = 0; b < Bn; b++) {
            float v = warp_sum(acc[b]);
            if (lane == 0) q0s[warp * Bn + b] = v;
        }
    }
    __syncthreads();

    // phase 2: partial qk[b][d] += sum_{e in tile} q0[e][b] * Wk[e][d]
    {
        float a0[Bn], a1[Bn], a2[Bn];
        #pragma unroll
        for (int b = 0; b < Bn; b++) { a0[b] = a1[b] = a2[b] = 0.f; }
        #pragma unroll
        for (int ee = 0; ee < 8; ee++) {
            const float* wkr = Wk + (size_t)(e0 + ee) * Dn;
            float w0 = wkr[tid], w1 = wkr[tid + 256], w2 = wkr[tid + 512];
            #pragma unroll
            for (int b = 0; b < Bn; b++) {
                float q = q0s[ee * Bn + b];
                a0[b] = fmaf(q, w0, a0[b]);
                a1[b] = fmaf(q, w1, a1[b]);
                a2[b] = fmaf(q, w2, a2[b]);
            }
        }
        #pragma unroll
        for (int b = 0; b < Bn; b++) {
            atomicAdd(&qk[b * Dn + tid],       a0[b]);
            atomicAdd(&qk[b * Dn + tid + 256], a1[b]);
            atomicAdd(&qk[b * Dn + tid + 512], a2[b]);
        }
    }
}

// ============ K2: streaming online-softmax, cp.async 4-stage pipeline ============
// 256 blocks x 256 threads; block = (batch b, chunk c of 128 rows).
__global__ void __launch_bounds__(256, 2) attn_stream(
    const float* __restrict__ b_in, const float* __restrict__ qk)
{
    extern __shared__ float4 smem4[];          // 96 KB: 4 stages x 8 rows
    __shared__ float msm[8], lsm[8];
    int tid = threadIdx.x, warp = tid >> 5, lane = tid & 31;
    int b = blockIdx.x >> 4, c = blockIdx.x & (CHUNKS_PER_B - 1);

    const float4* qkv = (const float4*)(qk + b * Dn);
    float4 qf[6];
    #pragma unroll
    for (int i = 0; i < 6; i++) qf[i] = qkv[i * 32 + lane];

    const float4* xb4 = (const float4*)b_in + ((size_t)b * Sn + (size_t)c * CHUNK_ROWS) * D4;
    unsigned int sbase = (unsigned int)__cvta_generic_to_shared(smem4);

    // prologue: fill stages 0..2
    #pragma unroll
    for (int s = 0; s < ATT_STAGES - 1; s++) {
        const float4* src = xb4 + (size_t)s * STAGE_F4;
        unsigned int dst = sbase + s * STAGE_BYTES;
        #pragma unroll
        for (int i = 0; i < 6; i++) {
            int idx = i * 256 + tid;
            cp_async16(dst + idx * 16, src + idx);
        }
        cp_commit();
    }

    float m = -CUDART_INF_F, l = 0.f;
    float4 acc[6];
    #pragma unroll
    for (int i = 0; i < 6; i++) acc[i] = make_float4(0.f, 0.f, 0.f, 0.f);

    for (int t = 0; t < NSTAGE_ITERS; t++) {
        if (t + ATT_STAGES - 1 < NSTAGE_ITERS) {
            int sn = t + ATT_STAGES - 1;
            const float4* src = xb4 + (size_t)sn * STAGE_F4;
            unsigned int dst = sbase + (sn & (ATT_STAGES - 1)) * STAGE_BYTES;
            #pragma unroll
            for (int i = 0; i < 6; i++) {
                int idx = i * 256 + tid;
                cp_async16(dst + idx * 16, src + idx);
            }
        }
        cp_commit();
        asm volatile("cp.async.wait_group 3;");
        __syncthreads();

        // warp w consumes row w of stage t
        const float4* row = smem4 + (size_t)(t & (ATT_STAGES - 1)) * STAGE_F4 + warp * D4;
        float4 cur[6];
        #pragma unroll
        for (int i = 0; i < 6; i++) cur[i] = row[i * 32 + lane];

        float dot = 0.f;
        #pragma unroll
        for (int i = 0; i < 6; i++) {
            dot = fmaf(qf[i].x, cur[i].x, dot);
            dot = fmaf(qf[i].y, cur[i].y, dot);
            dot = fmaf(qf[i].z, cur[i].z, dot);
            dot = fmaf(qf[i].w, cur[i].w, dot);
        }
        float score = warp_sum(dot) * NORM_CONST;

        float mn = fmaxf(m, score);
        float corr = __expf(m - mn);       // first row: exp(-inf)=0
        float w = __expf(score - mn);
        l = l * corr + w;
        #pragma unroll
        for (int i = 0; i < 6; i++) {
            acc[i].x = fmaf(w, cur[i].x, acc[i].x * corr);
            acc[i].y = fmaf(w, cur[i].y, acc[i].y * corr);
            acc[i].z = fmaf(w, cur[i].z, acc[i].z * corr);
            acc[i].w = fmaf(w, cur[i].w, acc[i].w * corr);
        }
        m = mn;
        __syncthreads();   // protect stage before next refill
    }

    // in-block merge of 8 warp partials -> 1 block partial
    float4* accsm = smem4;   // reuse stage memory (all stages consumed; sync above)
    #pragma unroll
    for (int i = 0; i < 6; i++) accsm[warp * D4 + i * 32 + lane] = acc[i];
    if (lane == 0) { msm[warp] = m; lsm[warp] = l; }
    __syncthreads();

    if (tid < D4) {
        float M = -CUDART_INF_F;
        #pragma unroll
        for (int w = 0; w < 8; w++) M = fmaxf(M, msm[w]);
        float L = 0.f;
        float4 s = make_float4(0.f, 0.f, 0.f, 0.f);
        #pragma unroll
        for (int w = 0; w < 8; w++) {
            float ef = __expf(msm[w] - M);
            L = fmaf(ef, lsm[w], L);
            float4 a = accsm[w * D4 + tid];
            s.x = fmaf(ef, a.x, s.x);
            s.y = fmaf(ef, a.y, s.y);
            s.z = fmaf(ef, a.z, s.z);
            s.w = fmaf(ef, a.w, s.w);
        }
        ((float4*)g_pacc)[(size_t)blockIdx.x * D4 + tid] = s;
        if (tid == 0) { g_pm[blockIdx.x] = M; g_pl[blockIdx.x] = L; }
    }
}

// ============ K3: split-softmax combine (16 partials/batch, float4) ============
__global__ void __launch_bounds__(192) combine2(float* __restrict__ c)
{
    int b = blockIdx.x;
    int d4 = threadIdx.x;                 // 0..191
    const float* pm = g_pm + b * CHUNKS_PER_B;
    const float* pl = g_pl + b * CHUNKS_PER_B;

    float M = -CUDART_INF_F;
    #pragma unroll
    for (int j = 0; j < CHUNKS_PER_B; j++) M = fmaxf(M, pm[j]);

    float L = 0.f;
    float4 s = make_float4(0.f, 0.f, 0.f, 0.f);
    const float4* pacc4 = (const float4*)g_pacc;
    #pragma unroll
    for (int j = 0; j < CHUNKS_PER_B; j++) {
        float ef = __expf(pm[j] - M);
        L = fmaf(ef, pl[j], L);
        float4 a = pacc4[(size_t)(b * CHUNKS_PER_B + j) * D4 + d4];
        s.x = fmaf(ef, a.x, s.x);
        s.y = fmaf(ef, a.y, s.y);
        s.z = fmaf(ef, a.z, s.z);
        s.w = fmaf(ef, a.w, s.w);
    }
    float inv = 1.f / L;
    float4 r = make_float4(s.x * inv, s.y * inv, s.z * inv, s.w * inv);
    ((float4*)c)[b * D4 + d4] = r;
}

// ============ K4: out[b][e] = Wv[e][:] . c[b][:]  (b-split) ============
// grid (96 e-chunks, 4 b-chunks) = 384 blocks; warp = one e-row x 4 batches.
// Only 12 KB of c per block (3 cp.async float4/thread); all SMs busy, short
// critical path; W rows L2-broadcast to the 4 b-chunk blocks.
__global__ void __launch_bounds__(256) matvec_wv(
    float* __restrict__ out, const float* __restrict__ W,
    const float* __restrict__ X)
{
    __shared__ float4 xs4[4 * D4];            // 12 KB: c for 4 batches
    int tid = threadIdx.x, warp = tid >> 5, lane = tid & 31;
    int b0 = blockIdx.y * 4;

    {
        unsigned int sb = (unsigned int)__cvta_generic_to_shared(xs4);
        const float4* src4 = (const float4*)X + (size_t)b0 * D4;  // 4 rows contiguous
        #pragma unroll
        for (int i = 0; i < 3; i++) {
            int idx = i * 256 + tid;          // 0..767 float4
            cp_async16(sb + idx * 16, src4 + idx);
        }
        cp_commit();
    }

    int e = blockIdx.x * 8 + warp;
    const float4* wr = (const float4*)(W + (size_t)e * Dn);
    float4 wf[6];
    #pragma unroll
    for (int i = 0; i < 6; i++) wf[i] = wr[i * 32 + lane];

    cp_wait_all();
    __syncthreads();

    float acc[4];
    #pragma unroll
    for (int b = 0; b < 4; b++) acc[b] = 0.f;
    #pragma unroll
    for (int i = 0; i < 6; i++) {
        float4 w = wf[i];
        #pragma unroll
        for (int b = 0; b < 4; b++) {
            float4 x = xs4[b * D4 + i * 32 + lane];
            acc[b] = fmaf(w.x, x.x, fmaf(w.y, x.y, fmaf(w.z, x.z, fmaf(w.w, x.w, acc[b]))));
        }
    }
    #pragma unroll
    for (int b = 0; b < 4; b++) {
        float v = warp_sum(acc[b]);
        if (lane == 0) out[(b0 + b) * Dn + e] = v;
    }
}

// ---------------- launch ----------------
extern "C" void kernel_launch(void* const* d_in, const int* in_sizes, int n_in,
                              void* d_out, int out_size)
{
    const float* b_in = (const float*)d_in[0];
    // d_in[1] = mask (int64): masks whole QUERY rows only; query row 0 is always
    // unmasked and the output only uses query row 0 -> mask is irrelevant.
    const float* Wq = (const float*)d_in[2];
    const float* Wk = (const float*)d_in[3];
    const float* Wv = (const float*)d_in[4];
    float* out = (float*)d_out;

    float* qk; cudaGetSymbolAddress((void**)&qk, g_qk);
    float* cc; cudaGetSymbolAddress((void**)&cc, g_c);

    cudaFuncSetAttribute(fused_q0qk, cudaFuncAttributeMaxDynamicSharedMemorySize, 49152);
    cudaFuncSetAttribute(attn_stream, cudaFuncAttributeMaxDynamicSharedMemorySize, ATT_STAGES * STAGE_BYTES);

    cudaMemsetAsync(qk, 0, Bn * Dn * sizeof(float), 0);
    fused_q0qk<<<96, 256, 49152>>>(qk, Wq, Wk, b_in);
    attn_stream<<<NPART, 256, ATT_STAGES * STAGE_BYTES>>>(b_in, qk);
    combine2<<<Bn, 192>>>(cc);
    matvec_wv<<<dim3(96, 4), 256>>>(out, Wv, cc);
}